// round 16
// baseline (speedup 1.0000x reference)
#include <cuda_runtime.h>
#include <cuda_fp16.h>
#include <math.h>
#include <float.h>
#include <stdint.h>

// Problem constants
#define BATCH  2
#define NSEQ   2048
#define DIM    2048
#define NH     32
#define HD     64
#define QKVN   (3*DIM)          // 6144
#define NTOK   (BATCH*NSEQ)     // 4096
#define NBH    (BATCH*NH)       // 64
#define LN_EPS 1e-6f

// ---------------------------------------------------------------------------
// Scratch (device globals -- no runtime allocation allowed)
// ---------------------------------------------------------------------------
__device__ __half g_qkvh[(size_t)NTOK * QKVN];         // 50.3 MB fp16
__device__ __half g_xh [(size_t)NTOK * DIM];           // 16.8 MB
__device__ __half g_wqkvh[(size_t)QKVN * DIM];         // 25.2 MB
__device__ __half g_wouth[(size_t)DIM * DIM];          // 8.4 MB
__device__ __half g_qh [(size_t)NBH * NSEQ * HD];      // 16.8 MB
__device__ __half g_kh [(size_t)NBH * NSEQ * HD];
__device__ __half g_vh [(size_t)NBH * NSEQ * HD];
__device__ __half g_ctxh[(size_t)NTOK * DIM];          // 16.8 MB
__device__ int    g_mask_mode;                         // 0=u8, 1=i32, 2=f32

// ---------------------------------------------------------------------------
// Mask dtype detection
// ---------------------------------------------------------------------------
__device__ __forceinline__ bool mask_at(const void* mp, int idx, int mode) {
    if (mode == 1) return ((const int*)mp)[idx] != 0;
    if (mode == 2) return ((const float*)mp)[idx] != 0.0f;
    return ((const unsigned char*)mp)[idx] != 0;
}

__global__ void detect_mask_kernel(const void* __restrict__ mp) {
    if (threadIdx.x != 0 || blockIdx.x != 0) return;
    const int* ip = (const int*)mp;
    bool iok = true;
    for (int i = 0; i < 1024; i++) {
        int v = ip[i];
        if (v != 0 && v != 1) { iok = false; break; }
    }
    if (iok) { g_mask_mode = 1; return; }
    const float* fp = (const float*)mp;
    bool fok = true;
    for (int i = 0; i < 1024; i++) {
        float v = fp[i];
        if (v != 0.0f && v != 1.0f) { fok = false; break; }
    }
    g_mask_mode = fok ? 2 : 0;
}

// ---------------------------------------------------------------------------
// Primitives
// ---------------------------------------------------------------------------
__device__ __forceinline__ void cpa16(void* sdst, const void* gsrc) {
    unsigned s = (unsigned)__cvta_generic_to_shared(sdst);
    asm volatile("cp.async.cg.shared.global [%0], [%1], 16;" :: "r"(s), "l"(gsrc));
}

__device__ __forceinline__ void mma_f16(float* c, const unsigned* a, const unsigned* b) {
    asm volatile(
        "mma.sync.aligned.m16n8k16.row.col.f32.f16.f16.f32 "
        "{%0,%1,%2,%3},{%4,%5,%6,%7},{%8,%9},{%0,%1,%2,%3};"
        : "+f"(c[0]), "+f"(c[1]), "+f"(c[2]), "+f"(c[3])
        : "r"(a[0]), "r"(a[1]), "r"(a[2]), "r"(a[3]), "r"(b[0]), "r"(b[1]));
}

__device__ __forceinline__ void ldm_x4(unsigned& r0, unsigned& r1,
                                       unsigned& r2, unsigned& r3, unsigned addr) {
    asm volatile("ldmatrix.sync.aligned.m8n8.x4.shared.b16 {%0,%1,%2,%3}, [%4];"
                 : "=r"(r0), "=r"(r1), "=r"(r2), "=r"(r3) : "r"(addr));
}

__device__ __forceinline__ void ldm_x4_trans(unsigned& r0, unsigned& r1,
                                             unsigned& r2, unsigned& r3, unsigned addr) {
    asm volatile("ldmatrix.sync.aligned.m8n8.x4.trans.shared.b16 {%0,%1,%2,%3}, [%4];"
                 : "=r"(r0), "=r"(r1), "=r"(r2), "=r"(r3) : "r"(addr));
}

// ---------------------------------------------------------------------------
// fp32 -> fp16 convert (vectorized)
// ---------------------------------------------------------------------------
__global__ __launch_bounds__(256)
void f2h_kernel(const float* __restrict__ in, __half* __restrict__ out, int n4)
{
    int idx = blockIdx.x * blockDim.x + threadIdx.x;
    if (idx >= n4) return;
    float4 v = ((const float4*)in)[idx];
    ((__half2*)out)[idx * 2]     = __floats2half2_rn(v.x, v.y);
    ((__half2*)out)[idx * 2 + 1] = __floats2half2_rn(v.z, v.w);
}

// ---------------------------------------------------------------------------
// fp16 NT GEMM: C[M,N] = A[M,K](f16) * B[N,K](f16)^T, OutT = float or __half.
// CTA tile 256x128, 256 threads = 8 warps x (64x64), K-tile 64 halves,
// double-buffered cp.async, ldmatrix frags. M%256==0, N%128==0, K%64==0.
// ---------------------------------------------------------------------------
#define GKH 64
#define SSH 72     // smem row stride in halves (144B, conflict-free frags)
#define A_ROWS 256
#define B_ROWS 128
#define A_STG (A_ROWS * SSH)   // halves per A stage
#define B_STG (B_ROWS * SSH)

template <typename OutT>
__global__ __launch_bounds__(256, 1)
void gemm_nt_f16(const __half* __restrict__ A, const __half* __restrict__ B,
                 OutT* __restrict__ C, int M, int N, int K)
{
    extern __shared__ __half hsm[];
    // layout: As[2][256][SSH] then Bs[2][128][SSH]
    __half* Asm = hsm;
    __half* Bsm = hsm + 2 * A_STG;
    const unsigned smem_u = (unsigned)__cvta_generic_to_shared(hsm);

    const int tid  = threadIdx.x;
    const int wid  = tid >> 5;
    const int lane = tid & 31;
    const int wm   = wid >> 1;          // 0..3 : 64-row slab
    const int wn   = wid & 1;           // 0..1 : 64-col slab

    const int ldRow = tid >> 3;         // 0..31
    const int ldCol = (tid & 7) * 8;    // half offset

    const __half* Ag = A + (size_t)(blockIdx.y * 256 + ldRow) * K + ldCol;
    const __half* Bg = B + (size_t)(blockIdx.x * 128 + ldRow) * K + ldCol;
    const size_t r32 = (size_t)32 * K;

    // ldmatrix per-lane addressing offsets
    const unsigned a_row = (unsigned)(wm * 64 + (lane & 15));
    const unsigned a_col = (unsigned)((lane >> 4) << 3);
    const unsigned b_row = (unsigned)(wn * 64 + (((lane >> 4) & 1) << 3) + (lane & 7));
    const unsigned b_col = (unsigned)(((lane >> 3) & 1) << 3);

    float acc[4][8][4];
#pragma unroll
    for (int i = 0; i < 4; i++)
#pragma unroll
        for (int j = 0; j < 8; j++)
#pragma unroll
            for (int c = 0; c < 4; c++) acc[i][j][c] = 0.0f;

    // prologue: stage 0 (A: 8 passes of 32 rows; B: 4 passes)
#pragma unroll
    for (int p = 0; p < 8; p++)
        cpa16(&Asm[(ldRow + 32*p) * SSH + ldCol], Ag + (size_t)p * r32);
#pragma unroll
    for (int p = 0; p < 4; p++)
        cpa16(&Bsm[(ldRow + 32*p) * SSH + ldCol], Bg + (size_t)p * r32);
    asm volatile("cp.async.commit_group;");

    const int KT = K / GKH;
    for (int kt = 0; kt < KT; kt++) {
        const int s = kt & 1;
        if (kt + 1 < KT) {
            const int kb = (kt + 1) * GKH;
            const int s1 = s ^ 1;
#pragma unroll
            for (int p = 0; p < 8; p++)
                cpa16(&Asm[s1 * A_STG + (ldRow + 32*p) * SSH + ldCol], Ag + (size_t)p * r32 + kb);
#pragma unroll
            for (int p = 0; p < 4; p++)
                cpa16(&Bsm[s1 * B_STG + (ldRow + 32*p) * SSH + ldCol], Bg + (size_t)p * r32 + kb);
            asm volatile("cp.async.commit_group;");
            asm volatile("cp.async.wait_group 1;");
        } else {
            asm volatile("cp.async.wait_group 0;");
        }
        __syncthreads();

        const unsigned abase = smem_u + (unsigned)(s * A_STG) * 2;
        const unsigned bbase = smem_u + (unsigned)(2 * A_STG + s * B_STG) * 2;

#pragma unroll
        for (int ks = 0; ks < 4; ks++) {
            const unsigned k0 = ks * 16;
            unsigned a[4][4];
#pragma unroll
            for (int mf = 0; mf < 4; mf++) {
                unsigned addr = abase + ((a_row + mf * 16) * SSH + k0 + a_col) * 2;
                ldm_x4(a[mf][0], a[mf][1], a[mf][2], a[mf][3], addr);
            }
            unsigned b[8][2];
#pragma unroll
            for (int p = 0; p < 4; p++) {
                unsigned addr = bbase + ((b_row + p * 16) * SSH + k0 + b_col) * 2;
                ldm_x4(b[2*p][0], b[2*p][1], b[2*p+1][0], b[2*p+1][1], addr);
            }
#pragma unroll
            for (int mf = 0; mf < 4; mf++)
#pragma unroll
                for (int nf = 0; nf < 8; nf++)
                    mma_f16(acc[mf][nf], a[mf], b[nf]);
        }
        __syncthreads();
    }

    const int g  = lane >> 2;
    const int tg = lane & 3;
#pragma unroll
    for (int mf = 0; mf < 4; mf++) {
        const int r0 = blockIdx.y * 256 + wm * 64 + mf * 16 + g;
#pragma unroll
        for (int nf = 0; nf < 8; nf++) {
            const int c0 = blockIdx.x * 128 + wn * 64 + nf * 8 + tg * 2;
            if (sizeof(OutT) == 4) {
                float* Cf = (float*)C;
                *(float2*)(Cf + (size_t)r0 * N + c0) =
                    make_float2(acc[mf][nf][0], acc[mf][nf][1]);
                *(float2*)(Cf + (size_t)(r0 + 8) * N + c0) =
                    make_float2(acc[mf][nf][2], acc[mf][nf][3]);
            } else {
                __half* Ch = (__half*)C;
                *(__half2*)(Ch + (size_t)r0 * N + c0) =
                    __floats2half2_rn(acc[mf][nf][0], acc[mf][nf][1]);
                *(__half2*)(Ch + (size_t)(r0 + 8) * N + c0) =
                    __floats2half2_rn(acc[mf][nf][2], acc[mf][nf][3]);
            }
        }
    }
}

// ---------------------------------------------------------------------------
// LayerNorm + RoPE + head-major relayout; fp16 in (qkv) / fp16 out.
// ---------------------------------------------------------------------------
__global__ __launch_bounds__(128)
void lnrope_kernel(const __half* __restrict__ qkv,
                   const float* __restrict__ qw, const float* __restrict__ qb,
                   const float* __restrict__ kw, const float* __restrict__ kb,
                   const float* __restrict__ freqs,
                   __half* __restrict__ Q, __half* __restrict__ K,
                   __half* __restrict__ V)
{
    const int wid  = blockIdx.x * 4 + (threadIdx.x >> 5);
    const int lane = threadIdx.x & 31;
    const int token = wid >> 5;
    const int h     = wid & 31;
    const int b     = token / NSEQ;
    const int nn    = token % NSEQ;
    const int bh    = b * NH + h;

    const __half* base = qkv + (size_t)token * QKVN + h * HD;
    float q1 = __half2float(base[lane]),          q2 = __half2float(base[32 + lane]);
    float k1 = __half2float(base[DIM + lane]),    k2 = __half2float(base[DIM + 32 + lane]);
    float v1 = __half2float(base[2*DIM + lane]),  v2 = __half2float(base[2*DIM + 32 + lane]);

    const float f  = freqs[nn * 32 + lane];
    const float cf = cosf(f), sf = sinf(f);

    __half* qo = Q + ((size_t)bh * NSEQ + nn) * HD;
    __half* ko = K + ((size_t)bh * NSEQ + nn) * HD;
    __half* vo = V + ((size_t)bh * NSEQ + nn) * HD;

    {
        float s = q1 + q2;
#pragma unroll
        for (int o = 16; o; o >>= 1) s += __shfl_xor_sync(0xffffffffu, s, o);
        float mean = s * (1.0f / HD);
        float d1 = q1 - mean, d2 = q2 - mean;
        float vs = d1 * d1 + d2 * d2;
#pragma unroll
        for (int o = 16; o; o >>= 1) vs += __shfl_xor_sync(0xffffffffu, vs, o);
        float inv = rsqrtf(vs * (1.0f / HD) + LN_EPS);
        float a = d1 * inv * qw[lane]      + qb[lane];
        float c = d2 * inv * qw[32 + lane] + qb[32 + lane];
        float p  = __shfl_xor_sync(0xffffffffu, a, 16);
        float rh = (lane < 16) ? -p : p;
        qo[lane]      = __float2half_rn(a * cf + rh * sf);
        qo[32 + lane] = __float2half_rn(c);
    }
    {
        float s = k1 + k2;
#pragma unroll
        for (int o = 16; o; o >>= 1) s += __shfl_xor_sync(0xffffffffu, s, o);
        float mean = s * (1.0f / HD);
        float d1 = k1 - mean, d2 = k2 - mean;
        float vs = d1 * d1 + d2 * d2;
#pragma unroll
        for (int o = 16; o; o >>= 1) vs += __shfl_xor_sync(0xffffffffu, vs, o);
        float inv = rsqrtf(vs * (1.0f / HD) + LN_EPS);
        float a = d1 * inv * kw[lane]      + kb[lane];
        float c = d2 * inv * kw[32 + lane] + kb[32 + lane];
        float p  = __shfl_xor_sync(0xffffffffu, a, 16);
        float rh = (lane < 16) ? -p : p;
        ko[lane]      = __float2half_rn(a * cf + rh * sf);
        ko[32 + lane] = __float2half_rn(c);
    }
    vo[lane]      = __float2half_rn(v1);
    vo[32 + lane] = __float2half_rn(v2);
}

// ---------------------------------------------------------------------------
// fp16 tensor-core flash attention: 256 threads, 8 warps x 32 query rows
// (Q-tile 256). K/P frags via ldmatrix; V via ldmatrix.trans. (unchanged)
// ---------------------------------------------------------------------------
#define AKST 72

__global__ __launch_bounds__(256, 1)
void attn_f16_kernel(const __half* __restrict__ Qg, const __half* __restrict__ Kg,
                     const __half* __restrict__ Vg, const void* __restrict__ maskp,
                     __half* __restrict__ ctx)
{
    extern __shared__ __half hsm[];
    __half* Ks = hsm;                         // [64][AKST]
    __half* Vs = hsm + 64*AKST;               // [64][AKST]
    __half* Ps = hsm + 2*64*AKST;             // [256][AKST]
    float*  mk = (float*)(hsm + 2*64*AKST + 256*AKST);   // [64]

    const int tid  = threadIdx.x;
    const int wid  = tid >> 5;
    const int lane = tid & 31;
    const int g    = lane >> 2;
    const int tg   = lane & 3;
    const int rbase = wid * 32;

    const int bh   = blockIdx.y;
    const int b    = bh >> 5;
    const int head = bh & 31;
    const int qbase = blockIdx.x * 256;
    const int mode = g_mask_mode;
    const float scale = 0.125f;

    const __half* Kbase = Kg + (size_t)bh * NSEQ * HD;
    const __half* Vbase = Vg + (size_t)bh * NSEQ * HD;

    const unsigned ks_u = (unsigned)__cvta_generic_to_shared(Ks);
    const unsigned vs_u = (unsigned)__cvta_generic_to_shared(Vs);
    const unsigned ps_u = (unsigned)__cvta_generic_to_shared(Ps);

    const unsigned arow = (unsigned)(lane & 15);
    const unsigned acol = (unsigned)((lane >> 4) << 3);
    const unsigned brow = (unsigned)((((lane >> 4) & 1) << 3) + (lane & 7));
    const unsigned bcol = (unsigned)(((lane >> 3) & 1) << 3);

    {
        const __half* Qrow = Qg + ((size_t)bh * NSEQ + qbase) * HD;
#pragma unroll
        for (int t = 0; t < 8; t++) {
            int lin = tid + t * 256;
            int r = lin >> 3, c8 = lin & 7;
            *(uint4*)&Ps[r * AKST + c8 * 8] = *(const uint4*)(Qrow + (size_t)r * HD + c8 * 8);
        }
    }
    __syncthreads();

    unsigned qf[2][4][4];
#pragma unroll
    for (int mf = 0; mf < 2; mf++) {
#pragma unroll
        for (int ks = 0; ks < 4; ks++) {
            unsigned addr = ps_u + (((unsigned)(rbase + mf*16) + arow) * AKST + ks*16 + acol) * 2;
            ldm_x4(qf[mf][ks][0], qf[mf][ks][1], qf[mf][ks][2], qf[mf][ks][3], addr);
        }
    }
    __syncthreads();

    float o[2][8][4];
#pragma unroll
    for (int mf = 0; mf < 2; mf++)
#pragma unroll
        for (int nf = 0; nf < 8; nf++)
#pragma unroll
            for (int c = 0; c < 4; c++) o[mf][nf][c] = 0.0f;

    float mrow[2][2] = {{-FLT_MAX, -FLT_MAX}, {-FLT_MAX, -FLT_MAX}};
    float lrow[2][2] = {{0.0f, 0.0f}, {0.0f, 0.0f}};

    const int jmax = qbase + 255;
    for (int j0 = 0; j0 <= jmax; j0 += 64) {
#pragma unroll
        for (int t = 0; t < 2; t++) {
            int lin = tid + t * 256;
            int r = lin >> 3, c8 = lin & 7;
            *(uint4*)&Ks[r * AKST + c8 * 8] = *(const uint4*)(Kbase + (size_t)(j0 + r) * HD + c8 * 8);
            *(uint4*)&Vs[r * AKST + c8 * 8] = *(const uint4*)(Vbase + (size_t)(j0 + r) * HD + c8 * 8);
        }
        if (tid < 64) mk[tid] = mask_at(maskp, b * NSEQ + j0 + tid, mode) ? 1.0f : 0.0f;
        __syncthreads();

        float s[2][8][4];
#pragma unroll
        for (int mf = 0; mf < 2; mf++)
#pragma unroll
            for (int nf = 0; nf < 8; nf++)
#pragma unroll
                for (int c = 0; c < 4; c++) s[mf][nf][c] = 0.0f;

#pragma unroll
        for (int ks = 0; ks < 4; ks++) {
            const unsigned k0 = ks * 16;
            unsigned bfr[8][2];
#pragma unroll
            for (int p = 0; p < 4; p++) {
                unsigned addr = ks_u + (((unsigned)(p * 16) + brow) * AKST + k0 + bcol) * 2;
                ldm_x4(bfr[2*p][0], bfr[2*p][1], bfr[2*p+1][0], bfr[2*p+1][1], addr);
            }
#pragma unroll
            for (int mf = 0; mf < 2; mf++)
#pragma unroll
                for (int nf = 0; nf < 8; nf++)
                    mma_f16(s[mf][nf], qf[mf][ks], bfr[nf]);
        }

#pragma unroll
        for (int mf = 0; mf < 2; mf++) {
            const int i0 = qbase + rbase + mf * 16 + g;
#pragma unroll
            for (int nf = 0; nf < 8; nf++) {
                const int jl = nf * 8 + 2 * tg;
                const int jg = j0 + jl;
                const float m0 = mk[jl], m1 = mk[jl + 1];
                s[mf][nf][0] = (m0 != 0.0f && jg     <= i0    ) ? s[mf][nf][0] * scale : -FLT_MAX;
                s[mf][nf][1] = (m1 != 0.0f && jg + 1 <= i0    ) ? s[mf][nf][1] * scale : -FLT_MAX;
                s[mf][nf][2] = (m0 != 0.0f && jg     <= i0 + 8) ? s[mf][nf][2] * scale : -FLT_MAX;
                s[mf][nf][3] = (m1 != 0.0f && jg + 1 <= i0 + 8) ? s[mf][nf][3] * scale : -FLT_MAX;
            }
        }

#pragma unroll
        for (int mf = 0; mf < 2; mf++) {
#pragma unroll
            for (int h = 0; h < 2; h++) {
                float rm = -FLT_MAX;
#pragma unroll
                for (int nf = 0; nf < 8; nf++)
                    rm = fmaxf(rm, fmaxf(s[mf][nf][h*2], s[mf][nf][h*2+1]));
                rm = fmaxf(rm, __shfl_xor_sync(0xffffffffu, rm, 1));
                rm = fmaxf(rm, __shfl_xor_sync(0xffffffffu, rm, 2));

                const float mo = mrow[mf][h];
                const float mn = fmaxf(mo, rm);
                const float corr = __expf(mo - mn);
                mrow[mf][h] = mn;
                float lr = lrow[mf][h] * corr;
#pragma unroll
                for (int nf = 0; nf < 8; nf++) {
                    o[mf][nf][h*2]   *= corr;
                    o[mf][nf][h*2+1] *= corr;
                }
                const int r = rbase + mf * 16 + g + h * 8;
#pragma unroll
                for (int nf = 0; nf < 8; nf++) {
                    float sv0 = s[mf][nf][h*2];
                    float sv1 = s[mf][nf][h*2+1];
                    float p0 = (sv0 < -1e37f) ? 0.0f : __expf(sv0 - mn);
                    float p1 = (sv1 < -1e37f) ? 0.0f : __expf(sv1 - mn);
                    lr += p0 + p1;
                    *(__half2*)&Ps[r * AKST + nf * 8 + 2 * tg] = __floats2half2_rn(p0, p1);
                }
                lrow[mf][h] = lr;
            }
        }
        __syncwarp();

#pragma unroll
        for (int ks = 0; ks < 4; ks++) {
            const unsigned k0 = ks * 16;
            unsigned af[2][4];
#pragma unroll
            for (int mf = 0; mf < 2; mf++) {
                unsigned addr = ps_u + (((unsigned)(rbase + mf*16) + arow) * AKST + k0 + acol) * 2;
                ldm_x4(af[mf][0], af[mf][1], af[mf][2], af[mf][3], addr);
            }
            unsigned bfr[8][2];
#pragma unroll
            for (int nf2 = 0; nf2 < 4; nf2++) {
                unsigned row = (unsigned)(k0 + (lane & 7) + ((lane >> 3) & 1) * 8);
                unsigned col = (unsigned)(nf2 * 16 + (lane >> 4) * 8);
                unsigned addr = vs_u + (row * AKST + col) * 2;
                ldm_x4_trans(bfr[nf2*2][0], bfr[nf2*2][1],
                             bfr[nf2*2+1][0], bfr[nf2*2+1][1], addr);
            }
#pragma unroll
            for (int mf = 0; mf < 2; mf++)
#pragma unroll
                for (int nf = 0; nf < 8; nf++)
                    mma_f16(o[mf][nf], af[mf], bfr[nf]);
        }
        __syncthreads();
    }

#pragma unroll
    for (int mf = 0; mf < 2; mf++) {
#pragma unroll
        for (int h = 0; h < 2; h++) {
            float lt = lrow[mf][h];
            lt += __shfl_xor_sync(0xffffffffu, lt, 1);
            lt += __shfl_xor_sync(0xffffffffu, lt, 2);

            if (lt == 0.0f) {
                for (int j = 0; j < NSEQ; j++) {
                    const __half* vp = Vbase + (size_t)j * HD;
#pragma unroll
                    for (int nf = 0; nf < 8; nf++) {
                        const int d = nf * 8 + 2 * tg;
                        o[mf][nf][h*2]   += __half2float(vp[d]);
                        o[mf][nf][h*2+1] += __half2float(vp[d + 1]);
                    }
                }
                lt = (float)NSEQ;
            }
            const float inv = 1.0f / lt;
            const int i0 = qbase + rbase + mf * 16 + g + h * 8;
            __half* op = ctx + ((size_t)(b * NSEQ + i0)) * DIM + head * HD;
#pragma unroll
            for (int nf = 0; nf < 8; nf++) {
                *(__half2*)(op + nf * 8 + 2 * tg) =
                    __floats2half2_rn(o[mf][nf][h*2] * inv, o[mf][nf][h*2+1] * inv);
            }
        }
    }
}

// ---------------------------------------------------------------------------
// Zero masked output rows
// ---------------------------------------------------------------------------
__global__ void apply_mask_out(float* __restrict__ out, const void* __restrict__ maskp)
{
    const int mode = g_mask_mode;
    const int idx = blockIdx.x * blockDim.x + threadIdx.x;
    const int total4 = NTOK * (DIM / 4);
    if (idx >= total4) return;
    const int token = idx / (DIM / 4);
    if (!mask_at(maskp, token, mode)) {
        ((float4*)out)[idx] = make_float4(0.f, 0.f, 0.f, 0.f);
    }
}

// ---------------------------------------------------------------------------
// Launcher
// ---------------------------------------------------------------------------
extern "C" void kernel_launch(void* const* d_in, const int* in_sizes, int n_in,
                              void* d_out, int out_size)
{
    const float* x     = (const float*)d_in[0];
    const float* Wqkv  = (const float*)d_in[1];
    const float* Wout  = (const float*)d_in[2];
    const float* qlnw  = (const float*)d_in[3];
    const float* qlnb  = (const float*)d_in[4];
    const float* klnw  = (const float*)d_in[5];
    const float* klnb  = (const float*)d_in[6];
    const float* freqs = (const float*)d_in[7];
    const void*  mask  = d_in[8];
    float* out = (float*)d_out;

    __half *qkvh, *xh, *wqkvh, *wouth, *qh, *kh, *vh, *ctxh;
    cudaGetSymbolAddress((void**)&qkvh,  g_qkvh);
    cudaGetSymbolAddress((void**)&xh,    g_xh);
    cudaGetSymbolAddress((void**)&wqkvh, g_wqkvh);
    cudaGetSymbolAddress((void**)&wouth, g_wouth);
    cudaGetSymbolAddress((void**)&qh,    g_qh);
    cudaGetSymbolAddress((void**)&kh,    g_kh);
    cudaGetSymbolAddress((void**)&vh,    g_vh);
    cudaGetSymbolAddress((void**)&ctxh,  g_ctxh);

    const int gemm_smem = 2 * (A_STG + B_STG) * (int)sizeof(__half);        // 110592
    const int attn_smem = (2*64*AKST + 256*AKST) * (int)sizeof(__half) + 64 * (int)sizeof(float);
    cudaFuncSetAttribute(gemm_nt_f16<float>,  cudaFuncAttributeMaxDynamicSharedMemorySize, gemm_smem);
    cudaFuncSetAttribute(gemm_nt_f16<__half>, cudaFuncAttributeMaxDynamicSharedMemorySize, gemm_smem);
    cudaFuncSetAttribute(attn_f16_kernel,     cudaFuncAttributeMaxDynamicSharedMemorySize, attn_smem);

    detect_mask_kernel<<<1, 32>>>(mask);

    // fp32 -> fp16 operand conversion
    {
        int n4;
        n4 = (NTOK * DIM) / 4;
        f2h_kernel<<<(n4 + 255) / 256, 256>>>(x, xh, n4);
        n4 = (QKVN * DIM) / 4;
        f2h_kernel<<<(n4 + 255) / 256, 256>>>(Wqkv, wqkvh, n4);
        n4 = (DIM * DIM) / 4;
        f2h_kernel<<<(n4 + 255) / 256, 256>>>(Wout, wouth, n4);
    }

    // qkv = x @ W_qkv^T   (fp16 MMA, fp16 out)
    gemm_nt_f16<__half><<<dim3(QKVN / 128, NTOK / 256), 256, gemm_smem>>>(
        xh, wqkvh, qkvh, NTOK, QKVN, DIM);

    // per-head LN + RoPE + relayout (fp16 in/out)
    lnrope_kernel<<<(NTOK * NH) / 4, 128>>>(qkvh, qlnw, qlnb, klnw, klnb, freqs, qh, kh, vh);

    // fp16 tensor-core attention
    attn_f16_kernel<<<dim3(NSEQ / 256, NBH), 256, attn_smem>>>(qh, kh, vh, mask, ctxh);

    // out = ctx @ W_out^T  (fp16 MMA, fp32 out)
    gemm_nt_f16<float><<<dim3(DIM / 128, NTOK / 256), 256, gemm_smem>>>(
        ctxh, wouth, out, NTOK, DIM, DIM);

    // zero masked rows
    apply_mask_out<<<(NTOK * (DIM / 4) + 255) / 256, 256>>>(out, mask);
}

// round 17
// speedup vs baseline: 1.0468x; 1.0468x over previous
#include <cuda_runtime.h>
#include <cuda_fp16.h>
#include <math.h>
#include <float.h>
#include <stdint.h>

// Problem constants
#define BATCH  2
#define NSEQ   2048
#define DIM    2048
#define NH     32
#define HD     64
#define QKVN   (3*DIM)          // 6144
#define NTOK   (BATCH*NSEQ)     // 4096
#define NBH    (BATCH*NH)       // 64
#define LN_EPS 1e-6f

// ---------------------------------------------------------------------------
// Scratch (device globals -- no runtime allocation allowed)
// ---------------------------------------------------------------------------
__device__ __half g_qkvh[(size_t)NTOK * QKVN];         // 50.3 MB fp16
__device__ __half g_xh [(size_t)NTOK * DIM];           // 16.8 MB
__device__ __half g_wqkvh[(size_t)QKVN * DIM];         // 25.2 MB
__device__ __half g_wouth[(size_t)DIM * DIM];          // 8.4 MB
__device__ __half g_qh [(size_t)NBH * NSEQ * HD];      // 16.8 MB
__device__ __half g_kh [(size_t)NBH * NSEQ * HD];
__device__ __half g_vh [(size_t)NBH * NSEQ * HD];
__device__ __half g_ctxh[(size_t)NTOK * DIM];          // 16.8 MB
__device__ int    g_mask_mode;                         // 0=u8, 1=i32, 2=f32

// ---------------------------------------------------------------------------
// Mask dtype detection
// ---------------------------------------------------------------------------
__device__ __forceinline__ bool mask_at(const void* mp, int idx, int mode) {
    if (mode == 1) return ((const int*)mp)[idx] != 0;
    if (mode == 2) return ((const float*)mp)[idx] != 0.0f;
    return ((const unsigned char*)mp)[idx] != 0;
}

__global__ void detect_mask_kernel(const void* __restrict__ mp) {
    if (threadIdx.x != 0 || blockIdx.x != 0) return;
    const int* ip = (const int*)mp;
    bool iok = true;
    for (int i = 0; i < 1024; i++) {
        int v = ip[i];
        if (v != 0 && v != 1) { iok = false; break; }
    }
    if (iok) { g_mask_mode = 1; return; }
    const float* fp = (const float*)mp;
    bool fok = true;
    for (int i = 0; i < 1024; i++) {
        float v = fp[i];
        if (v != 0.0f && v != 1.0f) { fok = false; break; }
    }
    g_mask_mode = fok ? 2 : 0;
}

// ---------------------------------------------------------------------------
// Primitives
// ---------------------------------------------------------------------------
__device__ __forceinline__ void cpa16(void* sdst, const void* gsrc) {
    unsigned s = (unsigned)__cvta_generic_to_shared(sdst);
    asm volatile("cp.async.cg.shared.global [%0], [%1], 16;" :: "r"(s), "l"(gsrc));
}

__device__ __forceinline__ void mma_f16(float* c, const unsigned* a, const unsigned* b) {
    asm volatile(
        "mma.sync.aligned.m16n8k16.row.col.f32.f16.f16.f32 "
        "{%0,%1,%2,%3},{%4,%5,%6,%7},{%8,%9},{%0,%1,%2,%3};"
        : "+f"(c[0]), "+f"(c[1]), "+f"(c[2]), "+f"(c[3])
        : "r"(a[0]), "r"(a[1]), "r"(a[2]), "r"(a[3]), "r"(b[0]), "r"(b[1]));
}

__device__ __forceinline__ void ldm_x4(unsigned& r0, unsigned& r1,
                                       unsigned& r2, unsigned& r3, unsigned addr) {
    asm volatile("ldmatrix.sync.aligned.m8n8.x4.shared.b16 {%0,%1,%2,%3}, [%4];"
                 : "=r"(r0), "=r"(r1), "=r"(r2), "=r"(r3) : "r"(addr));
}

__device__ __forceinline__ void ldm_x4_trans(unsigned& r0, unsigned& r1,
                                             unsigned& r2, unsigned& r3, unsigned addr) {
    asm volatile("ldmatrix.sync.aligned.m8n8.x4.trans.shared.b16 {%0,%1,%2,%3}, [%4];"
                 : "=r"(r0), "=r"(r1), "=r"(r2), "=r"(r3) : "r"(addr));
}

// ---------------------------------------------------------------------------
// fp32 -> fp16 convert (vectorized)
// ---------------------------------------------------------------------------
__global__ __launch_bounds__(256)
void f2h_kernel(const float* __restrict__ in, __half* __restrict__ out, int n4)
{
    int idx = blockIdx.x * blockDim.x + threadIdx.x;
    if (idx >= n4) return;
    float4 v = ((const float4*)in)[idx];
    ((__half2*)out)[idx * 2]     = __floats2half2_rn(v.x, v.y);
    ((__half2*)out)[idx * 2 + 1] = __floats2half2_rn(v.z, v.w);
}

// ---------------------------------------------------------------------------
// fp16 NT GEMM (R15 proven config): C[M,N] = A[M,K] * B[N,K]^T.
// 128x128 tile, 128 threads (4 warps x 64x64), K-tile 64 halves, double-buffer
// cp.async, ldmatrix frags, 2 CTAs/SM. OutT = float or __half.
// ---------------------------------------------------------------------------
#define GKH 64
#define SSH 72     // smem row stride in halves (144B, conflict-free frags)

template <typename OutT>
__global__ __launch_bounds__(128, 2)
void gemm_nt_f16(const __half* __restrict__ A, const __half* __restrict__ B,
                 OutT* __restrict__ C, int M, int N, int K)
{
    extern __shared__ __half hsm[];
    __half (*As)[128][SSH] = (__half(*)[128][SSH])hsm;                  // [2][128][72]
    __half (*Bs)[128][SSH] = (__half(*)[128][SSH])(hsm + 2*128*SSH);
    const unsigned smem_u = (unsigned)__cvta_generic_to_shared(hsm);

    const int tid  = threadIdx.x;
    const int wid  = tid >> 5;
    const int lane = tid & 31;
    const int wm   = wid >> 1;
    const int wn   = wid & 1;

    const int ldRow = tid >> 3;
    const int ldCol = (tid & 7) * 8;

    const __half* Ag = A + (size_t)(blockIdx.y * 128 + ldRow) * K + ldCol;
    const __half* Bg = B + (size_t)(blockIdx.x * 128 + ldRow) * K + ldCol;
    const size_t r16 = (size_t)16 * K;

    const unsigned a_row = (unsigned)(wm * 64 + (lane & 15));
    const unsigned a_col = (unsigned)((lane >> 4) << 3);
    const unsigned b_row = (unsigned)(wn * 64 + (((lane >> 4) & 1) << 3) + (lane & 7));
    const unsigned b_col = (unsigned)(((lane >> 3) & 1) << 3);

    float acc[4][8][4];
#pragma unroll
    for (int i = 0; i < 4; i++)
#pragma unroll
        for (int j = 0; j < 8; j++)
#pragma unroll
            for (int c = 0; c < 4; c++) acc[i][j][c] = 0.0f;

#pragma unroll
    for (int p = 0; p < 8; p++) {
        cpa16(&As[0][ldRow + 16*p][ldCol], Ag + (size_t)p * r16);
        cpa16(&Bs[0][ldRow + 16*p][ldCol], Bg + (size_t)p * r16);
    }
    asm volatile("cp.async.commit_group;");

    const int KT = K / GKH;
    for (int kt = 0; kt < KT; kt++) {
        const int s = kt & 1;
        if (kt + 1 < KT) {
            const int kb = (kt + 1) * GKH;
#pragma unroll
            for (int p = 0; p < 8; p++) {
                cpa16(&As[s ^ 1][ldRow + 16*p][ldCol], Ag + (size_t)p * r16 + kb);
                cpa16(&Bs[s ^ 1][ldRow + 16*p][ldCol], Bg + (size_t)p * r16 + kb);
            }
            asm volatile("cp.async.commit_group;");
            asm volatile("cp.async.wait_group 1;");
        } else {
            asm volatile("cp.async.wait_group 0;");
        }
        __syncthreads();

        const unsigned abase = smem_u + (unsigned)(s * 128 * SSH) * 2;
        const unsigned bbase = smem_u + (unsigned)((2 + s) * 128 * SSH) * 2;

#pragma unroll
        for (int ks = 0; ks < 4; ks++) {
            const unsigned k0 = ks * 16;
            unsigned a[4][4];
#pragma unroll
            for (int mf = 0; mf < 4; mf++) {
                unsigned addr = abase + ((a_row + mf * 16) * SSH + k0 + a_col) * 2;
                ldm_x4(a[mf][0], a[mf][1], a[mf][2], a[mf][3], addr);
            }
            unsigned b[8][2];
#pragma unroll
            for (int p = 0; p < 4; p++) {
                unsigned addr = bbase + ((b_row + p * 16) * SSH + k0 + b_col) * 2;
                ldm_x4(b[2*p][0], b[2*p][1], b[2*p+1][0], b[2*p+1][1], addr);
            }
#pragma unroll
            for (int mf = 0; mf < 4; mf++)
#pragma unroll
                for (int nf = 0; nf < 8; nf++)
                    mma_f16(acc[mf][nf], a[mf], b[nf]);
        }
        __syncthreads();
    }

    const int g  = lane >> 2;
    const int tg = lane & 3;
#pragma unroll
    for (int mf = 0; mf < 4; mf++) {
        const int r0 = blockIdx.y * 128 + wm * 64 + mf * 16 + g;
#pragma unroll
        for (int nf = 0; nf < 8; nf++) {
            const int c0 = blockIdx.x * 128 + wn * 64 + nf * 8 + tg * 2;
            if (sizeof(OutT) == 4) {
                float* Cf = (float*)C;
                *(float2*)(Cf + (size_t)r0 * N + c0) =
                    make_float2(acc[mf][nf][0], acc[mf][nf][1]);
                *(float2*)(Cf + (size_t)(r0 + 8) * N + c0) =
                    make_float2(acc[mf][nf][2], acc[mf][nf][3]);
            } else {
                __half* Ch = (__half*)C;
                *(__half2*)(Ch + (size_t)r0 * N + c0) =
                    __floats2half2_rn(acc[mf][nf][0], acc[mf][nf][1]);
                *(__half2*)(Ch + (size_t)(r0 + 8) * N + c0) =
                    __floats2half2_rn(acc[mf][nf][2], acc[mf][nf][3]);
            }
        }
    }
}

// ---------------------------------------------------------------------------
// LayerNorm + RoPE + head-major relayout; fp16 in (qkv) / fp16 out.
// ---------------------------------------------------------------------------
__global__ __launch_bounds__(128)
void lnrope_kernel(const __half* __restrict__ qkv,
                   const float* __restrict__ qw, const float* __restrict__ qb,
                   const float* __restrict__ kw, const float* __restrict__ kb,
                   const float* __restrict__ freqs,
                   __half* __restrict__ Q, __half* __restrict__ K,
                   __half* __restrict__ V)
{
    const int wid  = blockIdx.x * 4 + (threadIdx.x >> 5);
    const int lane = threadIdx.x & 31;
    const int token = wid >> 5;
    const int h     = wid & 31;
    const int b     = token / NSEQ;
    const int nn    = token % NSEQ;
    const int bh    = b * NH + h;

    const __half* base = qkv + (size_t)token * QKVN + h * HD;
    float q1 = __half2float(base[lane]),          q2 = __half2float(base[32 + lane]);
    float k1 = __half2float(base[DIM + lane]),    k2 = __half2float(base[DIM + 32 + lane]);
    float v1 = __half2float(base[2*DIM + lane]),  v2 = __half2float(base[2*DIM + 32 + lane]);

    const float f  = freqs[nn * 32 + lane];
    const float cf = cosf(f), sf = sinf(f);

    __half* qo = Q + ((size_t)bh * NSEQ + nn) * HD;
    __half* ko = K + ((size_t)bh * NSEQ + nn) * HD;
    __half* vo = V + ((size_t)bh * NSEQ + nn) * HD;

    {
        float s = q1 + q2;
#pragma unroll
        for (int o = 16; o; o >>= 1) s += __shfl_xor_sync(0xffffffffu, s, o);
        float mean = s * (1.0f / HD);
        float d1 = q1 - mean, d2 = q2 - mean;
        float vs = d1 * d1 + d2 * d2;
#pragma unroll
        for (int o = 16; o; o >>= 1) vs += __shfl_xor_sync(0xffffffffu, vs, o);
        float inv = rsqrtf(vs * (1.0f / HD) + LN_EPS);
        float a = d1 * inv * qw[lane]      + qb[lane];
        float c = d2 * inv * qw[32 + lane] + qb[32 + lane];
        float p  = __shfl_xor_sync(0xffffffffu, a, 16);
        float rh = (lane < 16) ? -p : p;
        qo[lane]      = __float2half_rn(a * cf + rh * sf);
        qo[32 + lane] = __float2half_rn(c);
    }
    {
        float s = k1 + k2;
#pragma unroll
        for (int o = 16; o; o >>= 1) s += __shfl_xor_sync(0xffffffffu, s, o);
        float mean = s * (1.0f / HD);
        float d1 = k1 - mean, d2 = k2 - mean;
        float vs = d1 * d1 + d2 * d2;
#pragma unroll
        for (int o = 16; o; o >>= 1) vs += __shfl_xor_sync(0xffffffffu, vs, o);
        float inv = rsqrtf(vs * (1.0f / HD) + LN_EPS);
        float a = d1 * inv * kw[lane]      + kb[lane];
        float c = d2 * inv * kw[32 + lane] + kb[32 + lane];
        float p  = __shfl_xor_sync(0xffffffffu, a, 16);
        float rh = (lane < 16) ? -p : p;
        ko[lane]      = __float2half_rn(a * cf + rh * sf);
        ko[32 + lane] = __float2half_rn(c);
    }
    vo[lane]      = __float2half_rn(v1);
    vo[32 + lane] = __float2half_rn(v2);
}

// ---------------------------------------------------------------------------
// fp16 flash attention with DOUBLE-BUFFERED cp.async K/V tiles.
// 256 threads, 8 warps x 32 query rows (Q-tile 256).
// ---------------------------------------------------------------------------
#define AKST 72
#define KV_TILE (64 * AKST)    // halves per K (or V) tile buffer

__global__ __launch_bounds__(256, 1)
void attn_f16_kernel(const __half* __restrict__ Qg, const __half* __restrict__ Kg,
                     const __half* __restrict__ Vg, const void* __restrict__ maskp,
                     __half* __restrict__ ctx)
{
    extern __shared__ __half hsm[];
    __half* Ks = hsm;                          // [2][64][AKST]
    __half* Vs = hsm + 2 * KV_TILE;            // [2][64][AKST]
    __half* Ps = hsm + 4 * KV_TILE;            // [256][AKST] (Q staging, then P)
    float*  mk = (float*)(hsm + 4 * KV_TILE + 256 * AKST);   // [2][64]

    const int tid  = threadIdx.x;
    const int wid  = tid >> 5;
    const int lane = tid & 31;
    const int g    = lane >> 2;
    const int tg   = lane & 3;
    const int rbase = wid * 32;

    const int bh   = blockIdx.y;
    const int b    = bh >> 5;
    const int head = bh & 31;
    const int qbase = blockIdx.x * 256;
    const int mode = g_mask_mode;
    const float scale = 0.125f;

    const __half* Kbase = Kg + (size_t)bh * NSEQ * HD;
    const __half* Vbase = Vg + (size_t)bh * NSEQ * HD;

    const unsigned ks_u = (unsigned)__cvta_generic_to_shared(Ks);
    const unsigned vs_u = (unsigned)__cvta_generic_to_shared(Vs);
    const unsigned ps_u = (unsigned)__cvta_generic_to_shared(Ps);

    const unsigned arow = (unsigned)(lane & 15);
    const unsigned acol = (unsigned)((lane >> 4) << 3);
    const unsigned brow = (unsigned)((((lane >> 4) & 1) << 3) + (lane & 7));
    const unsigned bcol = (unsigned)(((lane >> 3) & 1) << 3);

    const int ldr = tid >> 3;        // 0..31 (row within 32-row pass)
    const int ldc = (tid & 7) * 8;   // half offset

    // ---- stage Q tile into Ps, extract A-fragments ----
    {
        const __half* Qrow = Qg + ((size_t)bh * NSEQ + qbase) * HD;
#pragma unroll
        for (int t = 0; t < 8; t++) {
            int lin = tid + t * 256;
            int r = lin >> 3, c8 = lin & 7;
            *(uint4*)&Ps[r * AKST + c8 * 8] = *(const uint4*)(Qrow + (size_t)r * HD + c8 * 8);
        }
    }
    __syncthreads();

    unsigned qf[2][4][4];
#pragma unroll
    for (int mf = 0; mf < 2; mf++) {
#pragma unroll
        for (int ks = 0; ks < 4; ks++) {
            unsigned addr = ps_u + (((unsigned)(rbase + mf*16) + arow) * AKST + ks*16 + acol) * 2;
            ldm_x4(qf[mf][ks][0], qf[mf][ks][1], qf[mf][ks][2], qf[mf][ks][3], addr);
        }
    }
    __syncthreads();

    float o[2][8][4];
#pragma unroll
    for (int mf = 0; mf < 2; mf++)
#pragma unroll
        for (int nf = 0; nf < 8; nf++)
#pragma unroll
            for (int c = 0; c < 4; c++) o[mf][nf][c] = 0.0f;

    float mrow[2][2] = {{-FLT_MAX, -FLT_MAX}, {-FLT_MAX, -FLT_MAX}};
    float lrow[2][2] = {{0.0f, 0.0f}, {0.0f, 0.0f}};

    const int ntiles = qbase / 64 + 4;   // tiles of 64 keys up to qbase+255

    // prefetch tile 0 into buffer 0
    {
        const size_t j0 = 0;
#pragma unroll
        for (int t = 0; t < 2; t++) {
            int r = ldr + t * 32;
            cpa16(&Ks[0 * KV_TILE + r * AKST + ldc], Kbase + (j0 + r) * HD + ldc);
            cpa16(&Vs[0 * KV_TILE + r * AKST + ldc], Vbase + (j0 + r) * HD + ldc);
        }
        if (tid < 64) mk[tid] = mask_at(maskp, b * NSEQ + tid, mode) ? 1.0f : 0.0f;
        asm volatile("cp.async.commit_group;");
    }

    for (int it = 0; it < ntiles; it++) {
        const int s = it & 1;
        const int j0 = it * 64;

        // prefetch next tile into the other buffer, then wait for current
        if (it + 1 < ntiles) {
            const int s1 = s ^ 1;
            const size_t jn = (size_t)(it + 1) * 64;
#pragma unroll
            for (int t = 0; t < 2; t++) {
                int r = ldr + t * 32;
                cpa16(&Ks[s1 * KV_TILE + r * AKST + ldc], Kbase + (jn + r) * HD + ldc);
                cpa16(&Vs[s1 * KV_TILE + r * AKST + ldc], Vbase + (jn + r) * HD + ldc);
            }
            if (tid < 64)
                mk[s1 * 64 + tid] = mask_at(maskp, b * NSEQ + (int)jn + tid, mode) ? 1.0f : 0.0f;
            asm volatile("cp.async.commit_group;");
            asm volatile("cp.async.wait_group 1;");
        } else {
            asm volatile("cp.async.wait_group 0;");
        }
        __syncthreads();

        const unsigned kbuf = ks_u + (unsigned)(s * KV_TILE) * 2;
        const unsigned vbuf = vs_u + (unsigned)(s * KV_TILE) * 2;
        const float* mkc = mk + s * 64;

        // ---- S = Q K^T ----
        float sacc[2][8][4];
#pragma unroll
        for (int mf = 0; mf < 2; mf++)
#pragma unroll
            for (int nf = 0; nf < 8; nf++)
#pragma unroll
                for (int c = 0; c < 4; c++) sacc[mf][nf][c] = 0.0f;

#pragma unroll
        for (int ks = 0; ks < 4; ks++) {
            const unsigned k0 = ks * 16;
            unsigned bfr[8][2];
#pragma unroll
            for (int p = 0; p < 4; p++) {
                unsigned addr = kbuf + (((unsigned)(p * 16) + brow) * AKST + k0 + bcol) * 2;
                ldm_x4(bfr[2*p][0], bfr[2*p][1], bfr[2*p+1][0], bfr[2*p+1][1], addr);
            }
#pragma unroll
            for (int mf = 0; mf < 2; mf++)
#pragma unroll
                for (int nf = 0; nf < 8; nf++)
                    mma_f16(sacc[mf][nf], qf[mf][ks], bfr[nf]);
        }

        // ---- scale + key-mask + causal ----
#pragma unroll
        for (int mf = 0; mf < 2; mf++) {
            const int i0 = qbase + rbase + mf * 16 + g;
#pragma unroll
            for (int nf = 0; nf < 8; nf++) {
                const int jl = nf * 8 + 2 * tg;
                const int jg = j0 + jl;
                const float m0 = mkc[jl], m1 = mkc[jl + 1];
                sacc[mf][nf][0] = (m0 != 0.0f && jg     <= i0    ) ? sacc[mf][nf][0] * scale : -FLT_MAX;
                sacc[mf][nf][1] = (m1 != 0.0f && jg + 1 <= i0    ) ? sacc[mf][nf][1] * scale : -FLT_MAX;
                sacc[mf][nf][2] = (m0 != 0.0f && jg     <= i0 + 8) ? sacc[mf][nf][2] * scale : -FLT_MAX;
                sacc[mf][nf][3] = (m1 != 0.0f && jg + 1 <= i0 + 8) ? sacc[mf][nf][3] * scale : -FLT_MAX;
            }
        }

        // ---- streaming softmax; write fp16 P to warp-private rows ----
#pragma unroll
        for (int mf = 0; mf < 2; mf++) {
#pragma unroll
            for (int h = 0; h < 2; h++) {
                float rm = -FLT_MAX;
#pragma unroll
                for (int nf = 0; nf < 8; nf++)
                    rm = fmaxf(rm, fmaxf(sacc[mf][nf][h*2], sacc[mf][nf][h*2+1]));
                rm = fmaxf(rm, __shfl_xor_sync(0xffffffffu, rm, 1));
                rm = fmaxf(rm, __shfl_xor_sync(0xffffffffu, rm, 2));

                const float mo = mrow[mf][h];
                const float mn = fmaxf(mo, rm);
                const float corr = __expf(mo - mn);
                mrow[mf][h] = mn;
                float lr = lrow[mf][h] * corr;
#pragma unroll
                for (int nf = 0; nf < 8; nf++) {
                    o[mf][nf][h*2]   *= corr;
                    o[mf][nf][h*2+1] *= corr;
                }
                const int r = rbase + mf * 16 + g + h * 8;
#pragma unroll
                for (int nf = 0; nf < 8; nf++) {
                    float sv0 = sacc[mf][nf][h*2];
                    float sv1 = sacc[mf][nf][h*2+1];
                    float p0 = (sv0 < -1e37f) ? 0.0f : __expf(sv0 - mn);
                    float p1 = (sv1 < -1e37f) ? 0.0f : __expf(sv1 - mn);
                    lr += p0 + p1;
                    *(__half2*)&Ps[r * AKST + nf * 8 + 2 * tg] = __floats2half2_rn(p0, p1);
                }
                lrow[mf][h] = lr;
            }
        }
        __syncwarp();

        // ---- O += P V ----
#pragma unroll
        for (int ks = 0; ks < 4; ks++) {
            const unsigned k0 = ks * 16;
            unsigned af[2][4];
#pragma unroll
            for (int mf = 0; mf < 2; mf++) {
                unsigned addr = ps_u + (((unsigned)(rbase + mf*16) + arow) * AKST + k0 + acol) * 2;
                ldm_x4(af[mf][0], af[mf][1], af[mf][2], af[mf][3], addr);
            }
            unsigned bfr[8][2];
#pragma unroll
            for (int nf2 = 0; nf2 < 4; nf2++) {
                unsigned row = (unsigned)(k0 + (lane & 7) + ((lane >> 3) & 1) * 8);
                unsigned col = (unsigned)(nf2 * 16 + (lane >> 4) * 8);
                unsigned addr = vbuf + (row * AKST + col) * 2;
                ldm_x4_trans(bfr[nf2*2][0], bfr[nf2*2][1],
                             bfr[nf2*2+1][0], bfr[nf2*2+1][1], addr);
            }
#pragma unroll
            for (int mf = 0; mf < 2; mf++)
#pragma unroll
                for (int nf = 0; nf < 8; nf++)
                    mma_f16(o[mf][nf], af[mf], bfr[nf]);
        }
        __syncthreads();
    }

    // ---- epilogue ----
#pragma unroll
    for (int mf = 0; mf < 2; mf++) {
#pragma unroll
        for (int h = 0; h < 2; h++) {
            float lt = lrow[mf][h];
            lt += __shfl_xor_sync(0xffffffffu, lt, 1);
            lt += __shfl_xor_sync(0xffffffffu, lt, 2);

            if (lt == 0.0f) {
                for (int j = 0; j < NSEQ; j++) {
                    const __half* vp = Vbase + (size_t)j * HD;
#pragma unroll
                    for (int nf = 0; nf < 8; nf++) {
                        const int d = nf * 8 + 2 * tg;
                        o[mf][nf][h*2]   += __half2float(vp[d]);
                        o[mf][nf][h*2+1] += __half2float(vp[d + 1]);
                    }
                }
                lt = (float)NSEQ;
            }
            const float inv = 1.0f / lt;
            const int i0 = qbase + rbase + mf * 16 + g + h * 8;
            __half* op = ctx + ((size_t)(b * NSEQ + i0)) * DIM + head * HD;
#pragma unroll
            for (int nf = 0; nf < 8; nf++) {
                *(__half2*)(op + nf * 8 + 2 * tg) =
                    __floats2half2_rn(o[mf][nf][h*2] * inv, o[mf][nf][h*2+1] * inv);
            }
        }
    }
}

// ---------------------------------------------------------------------------
// Zero masked output rows
// ---------------------------------------------------------------------------
__global__ void apply_mask_out(float* __restrict__ out, const void* __restrict__ maskp)
{
    const int mode = g_mask_mode;
    const int idx = blockIdx.x * blockDim.x + threadIdx.x;
    const int total4 = NTOK * (DIM / 4);
    if (idx >= total4) return;
    const int token = idx / (DIM / 4);
    if (!mask_at(maskp, token, mode)) {
        ((float4*)out)[idx] = make_float4(0.f, 0.f, 0.f, 0.f);
    }
}

// ---------------------------------------------------------------------------
// Launcher
// ---------------------------------------------------------------------------
extern "C" void kernel_launch(void* const* d_in, const int* in_sizes, int n_in,
                              void* d_out, int out_size)
{
    const float* x     = (const float*)d_in[0];
    const float* Wqkv  = (const float*)d_in[1];
    const float* Wout  = (const float*)d_in[2];
    const float* qlnw  = (const float*)d_in[3];
    const float* qlnb  = (const float*)d_in[4];
    const float* klnw  = (const float*)d_in[5];
    const float* klnb  = (const float*)d_in[6];
    const float* freqs = (const float*)d_in[7];
    const void*  mask  = d_in[8];
    float* out = (float*)d_out;

    __half *qkvh, *xh, *wqkvh, *wouth, *qh, *kh, *vh, *ctxh;
    cudaGetSymbolAddress((void**)&qkvh,  g_qkvh);
    cudaGetSymbolAddress((void**)&xh,    g_xh);
    cudaGetSymbolAddress((void**)&wqkvh, g_wqkvh);
    cudaGetSymbolAddress((void**)&wouth, g_wouth);
    cudaGetSymbolAddress((void**)&qh,    g_qh);
    cudaGetSymbolAddress((void**)&kh,    g_kh);
    cudaGetSymbolAddress((void**)&vh,    g_vh);
    cudaGetSymbolAddress((void**)&ctxh,  g_ctxh);

    const int gemm_smem = 4 * 128 * SSH * (int)sizeof(__half);              // 73728
    const int attn_smem = (4 * KV_TILE + 256 * AKST) * (int)sizeof(__half)
                        + 128 * (int)sizeof(float);                          // ~74.5 KB
    cudaFuncSetAttribute(gemm_nt_f16<float>,  cudaFuncAttributeMaxDynamicSharedMemorySize, gemm_smem);
    cudaFuncSetAttribute(gemm_nt_f16<__half>, cudaFuncAttributeMaxDynamicSharedMemorySize, gemm_smem);
    cudaFuncSetAttribute(attn_f16_kernel,     cudaFuncAttributeMaxDynamicSharedMemorySize, attn_smem);

    detect_mask_kernel<<<1, 32>>>(mask);

    // fp32 -> fp16 operand conversion
    {
        int n4;
        n4 = (NTOK * DIM) / 4;
        f2h_kernel<<<(n4 + 255) / 256, 256>>>(x, xh, n4);
        n4 = (QKVN * DIM) / 4;
        f2h_kernel<<<(n4 + 255) / 256, 256>>>(Wqkv, wqkvh, n4);
        n4 = (DIM * DIM) / 4;
        f2h_kernel<<<(n4 + 255) / 256, 256>>>(Wout, wouth, n4);
    }

    // qkv = x @ W_qkv^T   (fp16 MMA, fp16 out)
    gemm_nt_f16<__half><<<dim3(QKVN / 128, NTOK / 128), 128, gemm_smem>>>(
        xh, wqkvh, qkvh, NTOK, QKVN, DIM);

    // per-head LN + RoPE + relayout (fp16 in/out)
    lnrope_kernel<<<(NTOK * NH) / 4, 128>>>(qkvh, qlnw, qlnb, klnw, klnb, freqs, qh, kh, vh);

    // fp16 tensor-core attention (double-buffered K/V)
    attn_f16_kernel<<<dim3(NSEQ / 256, NBH), 256, attn_smem>>>(qh, kh, vh, mask, ctxh);

    // out = ctx @ W_out^T  (fp16 MMA, fp32 out)
    gemm_nt_f16<float><<<dim3(DIM / 128, NTOK / 128), 128, gemm_smem>>>(
        ctxh, wouth, out, NTOK, DIM, DIM);

    // zero masked rows
    apply_mask_out<<<(NTOK * (DIM / 4) + 255) / 256, 256>>>(out, mask);
}